// round 1
// baseline (speedup 1.0000x reference)
#include <cuda_runtime.h>

// Problem constants (fixed by setup_inputs: b=8, N=16384, d=128, T=64)
#define BDIM   8
#define NPIX   16384
#define DDIM   128
#define TDIM   64
#define NCAT   21
#define THRESHV 230.0f
#define TPAD   130          // floats per smem row (pad 2 -> conflict-free 8B reads)
#define TPAD2  65           // 64-bit elements per row

// Output packing: flattened outputs concatenated in return order, float32.
#define OFF_MASK (2752512u)                    // 8*16384*21
#define OFF_NCM  (OFF_MASK + 131072u)
#define OFF_MIND (OFF_NCM  + 131072u)
#define OFF_NC   (OFF_MIND + 131072u)

__global__ __launch_bounds__(64) void nnos_kernel(
    const float* __restrict__ frame,   // [8, 16384, 128] f32
    const float* __restrict__ tmpl,    // [64, 16384, 128] f32
    const int*   __restrict__ tclass,  // [64] int32
    float*       __restrict__ out)
{
    __shared__ float t_s[TDIM * TPAD];   // 33280 B
    __shared__ float x_s[BDIM * TPAD];   //  4160 B
    __shared__ float t2_s[TDIM];
    __shared__ float x2_s[BDIM];
    __shared__ float rd_s[2][BDIM];
    __shared__ int   ri_s[2][BDIM];
    __shared__ int   fcls_s[BDIM];
    __shared__ int   fmask_s[BDIM];

    const int n    = blockIdx.x;
    const int tid  = threadIdx.x;
    const int w    = tid >> 5;
    const int lane = tid & 31;

    // ---- Phase 1: load this pixel's template rows (32 per warp) + norms ----
    const size_t gbase = (size_t)n * DDIM + 4 * lane;  // 16B-aligned
    #pragma unroll 4
    for (int i = 0; i < 32; ++i) {
        const int r = w * 32 + i;
        float4 v = *(const float4*)(tmpl + (size_t)r * (NPIX * DDIM) + gbase);
        float* dst = t_s + r * TPAD + 4 * lane;
        *(float2*)(dst)     = make_float2(v.x, v.y);
        *(float2*)(dst + 2) = make_float2(v.z, v.w);
        float sq = v.x*v.x + v.y*v.y + v.z*v.z + v.w*v.w;
        #pragma unroll
        for (int off = 16; off; off >>= 1)
            sq += __shfl_xor_sync(0xffffffffu, sq, off);
        if (lane == 0) t2_s[r] = sq;
    }
    // ---- frame rows (4 per warp) + norms ----
    #pragma unroll
    for (int i = 0; i < 4; ++i) {
        const int b = w * 4 + i;
        float4 v = *(const float4*)(frame + (size_t)b * (NPIX * DDIM) + gbase);
        float* dst = x_s + b * TPAD + 4 * lane;
        *(float2*)(dst)     = make_float2(v.x, v.y);
        *(float2*)(dst + 2) = make_float2(v.z, v.w);
        float sq = v.x*v.x + v.y*v.y + v.z*v.z + v.w*v.w;
        #pragma unroll
        for (int off = 16; off; off >>= 1)
            sq += __shfl_xor_sync(0xffffffffu, sq, off);
        if (lane == 0) x2_s[b] = sq;
    }
    __syncthreads();

    // ---- Phase 2: dot products. warp w -> templates [32w, 32w+32), lane -> one t.
    // 8 packed-f32x2 accumulators (one per batch). x broadcast from smem.
    const int t = w * 32 + lane;
    unsigned long long acc[BDIM];
    #pragma unroll
    for (int b = 0; b < BDIM; ++b) acc[b] = 0ULL;

    const unsigned long long* __restrict__ trow =
        (const unsigned long long*)(t_s) + (size_t)t * TPAD2;
    const unsigned long long* __restrict__ xall =
        (const unsigned long long*)(x_s);

    #pragma unroll 4
    for (int kp = 0; kp < DDIM / 2; ++kp) {
        unsigned long long tv = trow[kp];
        #pragma unroll
        for (int b = 0; b < BDIM; ++b) {
            unsigned long long xv = xall[b * TPAD2 + kp];
            asm("fma.rn.f32x2 %0, %1, %2, %0;" : "+l"(acc[b]) : "l"(xv), "l"(tv));
        }
    }

    // ---- Phase 3: distances + per-warp argmin over 32 lanes (lower idx wins ties)
    const float t2 = t2_s[t];
    #pragma unroll
    for (int b = 0; b < BDIM; ++b) {
        float lo = __uint_as_float((unsigned)(acc[b] & 0xffffffffULL));
        float hi = __uint_as_float((unsigned)(acc[b] >> 32));
        float d  = x2_s[b] - 2.0f * (lo + hi) + t2;
        int  idx = t;
        #pragma unroll
        for (int off = 16; off; off >>= 1) {
            float od = __shfl_xor_sync(0xffffffffu, d, off);
            int   oi = __shfl_xor_sync(0xffffffffu, idx, off);
            if (od < d || (od == d && oi < idx)) { d = od; idx = oi; }
        }
        if (lane == 0) { rd_s[w][b] = d; ri_s[w][b] = idx; }
    }
    __syncthreads();

    // ---- Phase 4: combine warp halves, write scalar outputs ----
    if (tid < BDIM) {
        const int b = tid;
        float d0 = rd_s[0][b], d1 = rd_s[1][b];
        int   i0 = ri_s[0][b], i1 = ri_s[1][b];
        float fd = d0; int fi = i0;
        if (d1 < d0) { fd = d1; fi = i1; }   // warp0 holds lower t -> ties go to i0
        int cls = tclass[fi];
        int msk = (fd <= THRESHV) ? 1 : 0;
        fcls_s[b]  = cls;
        fmask_s[b] = msk;
        const size_t bn = (size_t)b * NPIX + n;
        out[OFF_MASK + bn] = (float)msk;
        out[OFF_NCM  + bn] = (float)(msk ? cls : (NCAT - 1));
        out[OFF_MIND + bn] = fd;
        out[OFF_NC   + bn] = (float)cls;
    }
    __syncthreads();

    // ---- Phase 5: masked one-hot prediction, 8*21 floats per pixel ----
    for (int j = tid; j < BDIM * NCAT; j += 64) {
        int b = j / NCAT;
        int c = j - b * NCAT;
        float v = (fmask_s[b] && (c == fcls_s[b])) ? 1.0f : 0.0f;
        out[((size_t)b * NPIX + n) * NCAT + c] = v;
    }
}

extern "C" void kernel_launch(void* const* d_in, const int* in_sizes, int n_in,
                              void* d_out, int out_size) {
    const float* frame = (const float*)d_in[0];
    const float* tmpl  = (const float*)d_in[1];
    const int*   cls   = (const int*)d_in[2];
    float*       out   = (float*)d_out;
    (void)in_sizes; (void)n_in; (void)out_size;
    nnos_kernel<<<NPIX, 64>>>(frame, tmpl, cls, out);
}

// round 2
// speedup vs baseline: 1.3640x; 1.3640x over previous
#include <cuda_runtime.h>

// Problem constants (fixed by setup_inputs: b=8, N=16384, d=128, T=64)
#define BDIM   8
#define NPIX   16384
#define DDIM   128
#define TDIM   64
#define NCAT   21
#define THRESHV 230.0f

// Output packing: flattened outputs concatenated in return order, float32.
#define OFF_MASK (2752512u)                    // 8*16384*21
#define OFF_NCM  (OFF_MASK + 131072u)
#define OFF_MIND (OFF_NCM  + 131072u)
#define OFF_NC   (OFF_MIND + 131072u)

static __device__ __forceinline__ unsigned long long pk2(float a, float b) {
    unsigned long long r;
    asm("mov.b64 %0, {%1,%2};" : "=l"(r) : "f"(a), "f"(b));
    return r;
}
static __device__ __forceinline__ void upk2(unsigned long long v, float& a, float& b) {
    asm("mov.b64 {%0,%1}, %2;" : "=f"(a), "=f"(b) : "l"(v));
}
#define FMA2(acc, x, t) asm("fma.rn.f32x2 %0, %1, %2, %0;" : "+l"(acc) : "l"(x), "l"(t))

__global__ __launch_bounds__(256, 5) void nnos_kernel(
    const float* __restrict__ frame,   // [8, 16384, 128] f32
    const float* __restrict__ tmpl,    // [64, 16384, 128] f32
    const int*   __restrict__ tclass,  // [64] int32
    float*       __restrict__ out)
{
    // XOR-swizzled tiles: row stride 128 floats (512B), 16B granule g stored at
    // phys granule (g ^ (row & 7)). Conflict-free 16B LDS/STS, 16B-aligned.
    __shared__ __align__(16) float t_s[TDIM * DDIM];   // 32 KB
    __shared__ __align__(16) float x_s[BDIM * DDIM];   //  4 KB
    __shared__ float pd_s[4][BDIM];
    __shared__ int   pi_s[4][BDIM];
    __shared__ int   fcls_s[BDIM];
    __shared__ int   fmask_s[BDIM];

    const int n   = blockIdx.x;
    const int tid = threadIdx.x;

    // ---- Phase 1: pure streaming loads, swizzled stores. No reductions. ----
    const size_t pixbase = (size_t)n * DDIM;
    #pragma unroll 2
    for (int i = 0; i < 8; ++i) {                 // 64 rows x 32 granules / 256 thr
        const int idx = i * 256 + tid;
        const int r = idx >> 5, g = idx & 31;
        float4 v = *(const float4*)(tmpl + (size_t)r * (NPIX * DDIM) + pixbase + (g << 2));
        *(float4*)(t_s + r * DDIM + (((g ^ (r & 7)) << 2))) = v;
    }
    {
        const int r = tid >> 5, g = tid & 31;     // 8 rows x 32 granules = 256
        float4 v = *(const float4*)(frame + (size_t)r * (NPIX * DDIM) + pixbase + (g << 2));
        *(float4*)(x_s + r * DDIM + (((g ^ (r & 7)) << 2))) = v;
    }
    __syncthreads();

    // ---- Phase 2: warp w -> (t-group tg = w>>1 of 16 templates, batch-group bg = w&1).
    //      lane -> template t = 16*tg + (lane&15), batches b0 = 4*bg + 2*(lane>>4) + {0,1}.
    const int w    = tid >> 5;
    const int lane = tid & 31;
    const int tg   = w >> 1;
    const int bg   = w & 1;
    const int tt   = lane & 15;
    const int t    = tg * 16 + tt;
    const int b0   = bg * 4 + ((lane >> 4) << 1);

    const float* trow = t_s + t * DDIM;
    const float* xr0  = x_s + b0 * DDIM;
    const float* xr1  = x_s + (b0 + 1) * DDIM;
    const int swt  = (t  & 7) << 2;
    const int sw0  = (b0 & 7) << 2;
    const int sw1  = ((b0 + 1) & 7) << 2;

    unsigned long long acc0 = 0ULL, acc1 = 0ULL, t2a = 0ULL;

    #pragma unroll 4
    for (int kq = 0; kq < 32; ++kq) {
        const int o = kq << 2;
        float4 tv = *(const float4*)(trow + (o ^ swt));
        unsigned long long tvl = pk2(tv.x, tv.y);
        unsigned long long tvh = pk2(tv.z, tv.w);
        FMA2(t2a, tvl, tvl);
        FMA2(t2a, tvh, tvh);
        float4 xa = *(const float4*)(xr0 + (o ^ sw0));
        FMA2(acc0, pk2(xa.x, xa.y), tvl);
        FMA2(acc0, pk2(xa.z, xa.w), tvh);
        float4 xb = *(const float4*)(xr1 + (o ^ sw1));
        FMA2(acc1, pk2(xb.x, xb.y), tvl);
        FMA2(acc1, pk2(xb.z, xb.w), tvh);
    }

    // ---- Phase 3: d' = t2 - 2*xt (x2 added later; doesn't affect argmin).
    float t2lo, t2hi; upk2(t2a, t2lo, t2hi);
    const float t2 = t2lo + t2hi;
    #pragma unroll
    for (int j = 0; j < 2; ++j) {
        float lo, hi; upk2(j ? acc1 : acc0, lo, hi);
        float d = fmaf(-2.0f, lo + hi, t2);
        d = fmaf(-2.0f, hi, d - (-2.0f * hi));    // placeholder avoided below
        // recompute cleanly:
        d = fmaf(-2.0f, lo + hi, t2);
        int idx = t;
        #pragma unroll
        for (int off = 1; off <= 8; off <<= 1) {  // butterfly within 16-lane half
            float od = __shfl_xor_sync(0xffffffffu, d, off);
            int   oi = __shfl_xor_sync(0xffffffffu, idx, off);
            if (od < d || (od == d && oi < idx)) { d = od; idx = oi; }
        }
        if (tt == 0) { pd_s[tg][b0 + j] = d; pi_s[tg][b0 + j] = idx; }
    }
    __syncthreads();

    // ---- Phase 4: combine 4 t-groups, add x2, write scalar outputs ----
    if (tid < BDIM) {
        const int b = tid;
        float bd = pd_s[0][b]; int bi = pi_s[0][b];
        #pragma unroll
        for (int g = 1; g < 4; ++g) {
            float d = pd_s[g][b]; int i = pi_s[g][b];
            if (d < bd || (d == bd && i < bi)) { bd = d; bi = i; }
        }
        // x2 for this (b, n) from swizzled x_s
        const float* xr = x_s + b * DDIM;
        const int swb = (b & 7) << 2;
        float x2 = 0.0f;
        #pragma unroll 8
        for (int g = 0; g < 32; ++g) {
            float4 v = *(const float4*)(xr + ((g << 2) ^ swb));
            x2 += v.x * v.x + v.y * v.y + v.z * v.z + v.w * v.w;
        }
        const float fd = x2 + bd;
        const int cls = tclass[bi];
        const int msk = (fd <= THRESHV) ? 1 : 0;
        fcls_s[b]  = cls;
        fmask_s[b] = msk;
        const size_t bn = (size_t)b * NPIX + n;
        out[OFF_MASK + bn] = (float)msk;
        out[OFF_NCM  + bn] = (float)(msk ? cls : (NCAT - 1));
        out[OFF_MIND + bn] = fd;
        out[OFF_NC   + bn] = (float)cls;
    }
    __syncthreads();

    // ---- Phase 5: masked one-hot prediction (8*21 = 168 floats) ----
    if (tid < BDIM * NCAT) {
        const int b = tid / NCAT;
        const int c = tid - b * NCAT;
        const float v = (fmask_s[b] && (c == fcls_s[b])) ? 1.0f : 0.0f;
        out[((size_t)b * NPIX + n) * NCAT + c] = v;
    }
}

extern "C" void kernel_launch(void* const* d_in, const int* in_sizes, int n_in,
                              void* d_out, int out_size) {
    const float* frame = (const float*)d_in[0];
    const float* tmpl  = (const float*)d_in[1];
    const int*   cls   = (const int*)d_in[2];
    float*       out   = (float*)d_out;
    (void)in_sizes; (void)n_in; (void)out_size;
    nnos_kernel<<<NPIX, 256>>>(frame, tmpl, cls, out);
}

// round 3
// speedup vs baseline: 1.9827x; 1.4537x over previous
#include <cuda_runtime.h>

// Problem constants (fixed by setup_inputs: b=8, N=16384, d=128, T=64)
#define BDIM    8
#define NPIX    16384
#define DDIM    128
#define TDIM    64
#define NCAT    21
#define THRESHV 230.0f
#define TSTRIDE 132     // floats per smem row: 33 granules, 33 % 32 == 1 -> conflict-free
#define PSTRIDE 19      // partials row stride: gcd(19,32)=1 -> conflict-free scalar reads

// Output packing: flattened outputs concatenated in return order, float32.
#define OFF_MASK 2752512u                      // 8*16384*21
#define OFF_NCM  (OFF_MASK + 131072u)
#define OFF_MIND (OFF_NCM  + 131072u)
#define OFF_NC   (OFF_MIND + 131072u)

#define FMA2(acc, x, t) asm("fma.rn.f32x2 %0, %1, %2, %0;" : "+l"(acc) : "l"(x), "l"(t))

static __device__ __forceinline__ void upk2(unsigned long long v, float& a, float& b) {
    asm("mov.b64 {%0,%1}, %2;" : "=f"(a), "=f"(b) : "l"(v));
}

__global__ __launch_bounds__(256, 4) void nnos_kernel(
    const float* __restrict__ frame,   // [8, 16384, 128] f32
    const float* __restrict__ tmpl,    // [64, 16384, 128] f32
    const int*   __restrict__ tclass,  // [64] int32
    float*       __restrict__ out)
{
    __shared__ __align__(16) float t_s[TDIM * TSTRIDE];   // 33792 B
    __shared__ __align__(16) float x_s[BDIM * TSTRIDE];   //  4224 B
    __shared__ float part[TDIM * PSTRIDE];                 //  4864 B
    __shared__ float x2_s[BDIM];

    const int n    = blockIdx.x;
    const int tid  = threadIdx.x;
    const int w    = tid >> 5;
    const int lane = tid & 31;

    // ---- Phase 1a: stage templates via cp.async (no register round-trip) ----
    const size_t pixbase = (size_t)n * DDIM + 4 * lane;
    {
        #pragma unroll
        for (int i = 0; i < 8; ++i) {
            const int r = i * 8 + w;                       // warp w -> rows w, 8+w, ...
            const float* src = tmpl + (size_t)r * (NPIX * DDIM) + pixbase;
            unsigned dst = (unsigned)__cvta_generic_to_shared(t_s + r * TSTRIDE + 4 * lane);
            asm volatile("cp.async.cg.shared.global [%0], [%1], 16;\n" :: "r"(dst), "l"(src));
        }
        asm volatile("cp.async.commit_group;\n");
    }
    // ---- Phase 1b: frame row w -> smem + x2 reduction (overlaps async copies) ----
    {
        float4 v = *(const float4*)(frame + (size_t)w * (NPIX * DDIM) + pixbase);
        *(float4*)(x_s + w * TSTRIDE + 4 * lane) = v;
        float sq = v.x * v.x + v.y * v.y + v.z * v.z + v.w * v.w;
        #pragma unroll
        for (int off = 16; off; off >>= 1)
            sq += __shfl_xor_sync(0xffffffffu, sq, off);
        if (lane == 0) x2_s[w] = sq;
    }
    asm volatile("cp.async.wait_group 0;\n");
    __syncthreads();

    // ---- Phase 2: warp w -> (t-group c = w&3 of 16 templates, k-half kh = w>>2).
    //      lane -> template t = 16c + (lane&15), batches b = 4*(lane>>4) + {0..3}.
    {
        const int c  = w & 3;
        const int kh = w >> 2;
        const int tt = lane & 15;
        const int t  = c * 16 + tt;
        const int bh = lane >> 4;

        const float* trow = t_s + t * TSTRIDE + kh * 64;
        const float* xrow = x_s + (4 * bh) * TSTRIDE + kh * 64;

        unsigned long long a0 = 0, a1 = 0, a2 = 0, a3 = 0, t2a = 0;

        #pragma unroll
        for (int g = 0; g < 16; ++g) {
            ulonglong2 tv = *(const ulonglong2*)(trow + g * 4);
            FMA2(t2a, tv.x, tv.x);
            FMA2(t2a, tv.y, tv.y);
            ulonglong2 v0 = *(const ulonglong2*)(xrow + 0 * TSTRIDE + g * 4);
            FMA2(a0, v0.x, tv.x); FMA2(a0, v0.y, tv.y);
            ulonglong2 v1 = *(const ulonglong2*)(xrow + 1 * TSTRIDE + g * 4);
            FMA2(a1, v1.x, tv.x); FMA2(a1, v1.y, tv.y);
            ulonglong2 v2 = *(const ulonglong2*)(xrow + 2 * TSTRIDE + g * 4);
            FMA2(a2, v2.x, tv.x); FMA2(a2, v2.y, tv.y);
            ulonglong2 v3 = *(const ulonglong2*)(xrow + 3 * TSTRIDE + g * 4);
            FMA2(a3, v3.x, tv.x); FMA2(a3, v3.y, tv.y);
        }

        // collapse packed accs -> partial xt sums and t2, store to partials
        float lo, hi;
        float* pr = part + t * PSTRIDE + 8 * kh + 4 * bh;
        upk2(a0, lo, hi); pr[0] = lo + hi;
        upk2(a1, lo, hi); pr[1] = lo + hi;
        upk2(a2, lo, hi); pr[2] = lo + hi;
        upk2(a3, lo, hi); pr[3] = lo + hi;
        upk2(t2a, lo, hi);
        part[t * PSTRIDE + 16 + kh] = lo + hi;   // written by both bh lanes, same value
    }
    __syncthreads();

    // ---- Phase 3: warp w owns batch b = w. Lanes scan t = lane, lane+32,
    //      butterfly all-reduce argmin, fused epilogue. ----
    {
        const int b = w;
        const float* p0 = part + lane * PSTRIDE;
        const float* p1 = part + (lane + 32) * PSTRIDE;

        float xt0 = p0[b] + p0[8 + b];
        float d   = fmaf(-2.0f, xt0, p0[16] + p0[17]);
        int   idx = lane;
        float xt1 = p1[b] + p1[8 + b];
        float d1  = fmaf(-2.0f, xt1, p1[16] + p1[17]);
        if (d1 < d) { d = d1; idx = lane + 32; }          // tie -> lower idx kept

        #pragma unroll
        for (int off = 16; off; off >>= 1) {
            float od = __shfl_xor_sync(0xffffffffu, d, off);
            int   oi = __shfl_xor_sync(0xffffffffu, idx, off);
            if (od < d || (od == d && oi < idx)) { d = od; idx = oi; }
        }
        // all lanes now hold the (min, argmin)
        const int   cls = tclass[idx];
        const float fd  = x2_s[b] + d;
        const int   msk = (fd <= THRESHV) ? 1 : 0;
        const size_t bn = (size_t)b * NPIX + n;

        if (lane == 0) {
            out[OFF_MASK + bn] = (float)msk;
            out[OFF_NCM  + bn] = (float)(msk ? cls : (NCAT - 1));
            out[OFF_MIND + bn] = fd;
            out[OFF_NC   + bn] = (float)cls;
        }
        if (lane < NCAT)
            out[bn * NCAT + lane] = (msk && (lane == cls)) ? 1.0f : 0.0f;
    }
}

extern "C" void kernel_launch(void* const* d_in, const int* in_sizes, int n_in,
                              void* d_out, int out_size) {
    const float* frame = (const float*)d_in[0];
    const float* tmpl  = (const float*)d_in[1];
    const int*   cls   = (const int*)d_in[2];
    float*       out   = (float*)d_out;
    (void)in_sizes; (void)n_in; (void)out_size;
    nnos_kernel<<<NPIX, 256>>>(frame, tmpl, cls, out);
}